// round 10
// baseline (speedup 1.0000x reference)
#include <cuda_runtime.h>
#include <cstdint>

// BatchedHGNNLayer: out = diag(Dv^-1/2) H diag(De^-1) H^T diag(Dv^-1/2) x W^T + b
// B=8, N=4096, E=2048, C=128 fp32. mma.sync tf32 + cp.async.
// This round: 2 CTAs/SM on both GEMMs (gemm1 BM=64, gemm3 STG=3).

#define B_ 8
#define N_ 4096
#define E_ 2048
#define C_ 128
#define EPS 1e-6f

// ---------------- scratch ----------------------------------------------------
__device__ float g_DvInv[B_ * N_];
__device__ float g_Xs[(size_t)B_ * N_ * C_];    // rna(x * DvInv)
__device__ float g_M2T[(size_t)B_ * C_ * E_];   // rna((De^-1 H^T Xs) W^T)^T  [b][c2][e]

// ---------------- helpers ----------------------------------------------------
__device__ __forceinline__ float tf32r(float x) {
    uint32_t u;
    asm("cvt.rna.tf32.f32 %0, %1;" : "=r"(u) : "f"(x));
    return __uint_as_float(u);
}
__device__ __forceinline__ uint32_t tf32u(float x) {
    uint32_t u;
    asm("cvt.rna.tf32.f32 %0, %1;" : "=r"(u) : "f"(x));
    return u;
}
__device__ __forceinline__ uint32_t smem_u32(const void* p) {
    uint32_t a;
    asm("{ .reg .u64 t; cvta.to.shared.u64 t, %1; cvt.u32.u64 %0, t; }" : "=r"(a) : "l"(p));
    return a;
}
__device__ __forceinline__ void mma_tf32(float* c, const uint32_t* a, const uint32_t* b) {
    asm volatile(
        "mma.sync.aligned.m16n8k8.row.col.f32.tf32.tf32.f32 "
        "{%0,%1,%2,%3}, {%4,%5,%6,%7}, {%8,%9}, {%0,%1,%2,%3};"
        : "+f"(c[0]), "+f"(c[1]), "+f"(c[2]), "+f"(c[3])
        : "r"(a[0]), "r"(a[1]), "r"(a[2]), "r"(a[3]), "r"(b[0]), "r"(b[1]));
}
#define CP16(dst, src) \
    asm volatile("cp.async.cg.shared.global [%0], [%1], 16;" :: "r"(dst), "l"(src))
#define CP_COMMIT() asm volatile("cp.async.commit_group;" ::: "memory")
#define CP_WAIT(n)  asm volatile("cp.async.wait_group %0;" :: "n"(n) : "memory")
#define FU(x) __float_as_uint(x)

// ---------------- small kernels ----------------------------------------------
__global__ void dv_kernel(const float* __restrict__ Hg) {
    int row = blockIdx.x * 8 + threadIdx.y;
    const float4* src = (const float4*)(Hg + (size_t)row * E_);
    float s = 0.f;
    for (int i = threadIdx.x; i < E_ / 4; i += 32) {
        float4 v = src[i];
        s += (v.x + v.y) + (v.z + v.w);
    }
    #pragma unroll
    for (int o = 16; o; o >>= 1) s += __shfl_xor_sync(0xffffffffu, s, o);
    if (threadIdx.x == 0) g_DvInv[row] = rsqrtf(s + EPS);
}

__global__ void prep_x(const float* __restrict__ xg) {
    int i = blockIdx.x * 256 + threadIdx.x;
    int row = i >> 5;
    float dv = g_DvInv[row];
    float4 v = ((const float4*)xg)[i];
    float4 r;
    r.x = tf32r(v.x * dv); r.y = tf32r(v.y * dv);
    r.z = tf32r(v.z * dv); r.w = tf32r(v.w * dv);
    ((float4*)g_Xs)[i] = r;
}

// ---------------- GEMM1 (+fused De, +fused W M^T): BM=64, KM layout ----------
// M2T[b][c2][e-tile] = sum_c W[c2][c] * (De^-1 sum_n H[n][e] Xs[n][c])[e][c]
// grid (E_/64, 1, B_), 2 CTAs/SM.
#define TA1 (32 * 72 * 4)    // 9216
#define TB1 (32 * 136 * 4)   // 17408
#define DYN1 (4 * TA1 + 4 * TB1)  // 106496

__global__ __launch_bounds__(256, 2) void gemm1_kernel(const float* __restrict__ Hg,
                                                       const float* __restrict__ Wg) {
    extern __shared__ __align__(16) char ds[];
    __shared__ float deP[4][64];
    __shared__ float scl[64];

    const int tid = threadIdx.x, b = blockIdx.z, blk = blockIdx.x;
    const int lane = tid & 31, wid = tid >> 5;
    const int g = lane >> 2, tg = lane & 3;
    const int wm = wid & 1, wn = wid >> 1;

    const float* Ag = Hg + (size_t)b * N_ * E_;
    const float* Bg = g_Xs + (size_t)b * N_ * C_;
    const int acol = blk * 64;

    const uint32_t sA = smem_u32(ds), sB = sA + 4 * TA1;

    float acc[2][4][4];
    #pragma unroll
    for (int i = 0; i < 2; i++)
        #pragma unroll
        for (int j = 0; j < 4; j++)
            #pragma unroll
            for (int r = 0; r < 4; r++) acc[i][j][r] = 0.f;

    float deacc = 0.f;
    const int mcol = tid & 63, khalf = tid >> 6;

    auto issue = [&](int kt) {
        int buf = kt & 3;
        #pragma unroll
        for (int i = 0; i < 6; i++) {
            int ch = tid + 256 * i;
            if (i < 2) {                       // A: 512 chunks (32k x 64m)
                int k = ch >> 4, m4 = (ch & 15) * 4;
                CP16(sA + buf * TA1 + (k * 72 + m4) * 4,
                     Ag + (size_t)(kt * 32 + k) * E_ + acol + m4);
            } else {                           // B: 1024 chunks (32k x 128c)
                int c2 = ch - 512;
                int k = c2 >> 5, n4 = (c2 & 31) * 4;
                CP16(sB + buf * TB1 + (k * 136 + n4) * 4,
                     Bg + (size_t)(kt * 32 + k) * C_ + n4);
            }
        }
        CP_COMMIT();
    };

    const int KT = N_ / 32;   // 128
    issue(0); issue(1); issue(2);

    for (int kt = 0; kt < KT; kt++) {
        if (kt + 3 < KT) issue(kt + 3);
        int rem = KT - 1 - kt;
        if (rem >= 3)      CP_WAIT(3);
        else if (rem == 2) CP_WAIT(2);
        else if (rem == 1) CP_WAIT(1);
        else               CP_WAIT(0);
        __syncthreads();

        const float* As = (const float*)(ds + (size_t)(kt & 3) * TA1);
        const float* Bs = (const float*)(ds + (size_t)4 * TA1 + (size_t)(kt & 3) * TB1);

        {   // fused De from raw H: each thread sums 8 rows of its column
            float s = 0.f;
            #pragma unroll
            for (int j = 0; j < 8; j++) s += As[(khalf * 8 + j) * 72 + mcol];
            deacc += s;
        }

        #pragma unroll
        for (int ks = 0; ks < 32; ks += 8) {
            uint32_t af[2][4], bf[4][2];
            #pragma unroll
            for (int mt = 0; mt < 2; mt++) {
                int m = wm * 32 + mt * 16 + g;
                af[mt][0] = tf32u(As[(ks + tg) * 72 + m]);
                af[mt][1] = tf32u(As[(ks + tg) * 72 + m + 8]);
                af[mt][2] = tf32u(As[(ks + tg + 4) * 72 + m]);
                af[mt][3] = tf32u(As[(ks + tg + 4) * 72 + m + 8]);
            }
            #pragma unroll
            for (int nt = 0; nt < 4; nt++) {
                int n = wn * 32 + nt * 8 + g;
                bf[nt][0] = FU(Bs[(ks + tg) * 136 + n]);
                bf[nt][1] = FU(Bs[(ks + tg + 4) * 136 + n]);
            }
            #pragma unroll
            for (int mt = 0; mt < 2; mt++)
                #pragma unroll
                for (int nt = 0; nt < 4; nt++)
                    mma_tf32(acc[mt][nt], af[mt], bf[nt]);
        }
        __syncthreads();
    }

    // ---- epilogue: W load + De + in-CTA sub-GEMM M2T = W M^T ----
    float* Msm = (float*)ds;                     // [64][132]  = 33792 B
    float* Wsm = (float*)(ds + 4 * TA1);         // [128][132] = 67584 B (fits B-ring)
    {
        const uint32_t sW = smem_u32(Wsm);
        #pragma unroll
        for (int i = 0; i < 16; i++) {
            int ch = tid + 256 * i;              // 4096 chunks: 128 rows x 32
            int m = ch >> 5, q = ch & 31;
            CP16(sW + (m * 132 + q * 4) * 4, Wg + (size_t)m * C_ + q * 4);
        }
        CP_COMMIT();
    }
    deP[khalf][mcol] = deacc;
    __syncthreads();
    if (tid < 64)
        scl[tid] = 1.0f / (deP[0][tid] + deP[1][tid] + deP[2][tid] + deP[3][tid] + EPS);
    __syncthreads();

    #pragma unroll
    for (int mt = 0; mt < 2; mt++) {
        int r = wm * 32 + mt * 16 + g;
        float s0 = scl[r], s1 = scl[r + 8];
        #pragma unroll
        for (int nt = 0; nt < 4; nt++) {
            int col = wn * 32 + nt * 8 + tg * 2;
            float* c = acc[mt][nt];
            *(float2*)(Msm + r * 132 + col) =
                make_float2(tf32r(c[0] * s0), tf32r(c[1] * s0));
            *(float2*)(Msm + (r + 8) * 132 + col) =
                make_float2(tf32r(c[2] * s1), tf32r(c[3] * s1));
        }
    }
    CP_WAIT(0);
    __syncthreads();

    float acc2[4][2][4];
    #pragma unroll
    for (int i = 0; i < 4; i++)
        #pragma unroll
        for (int j = 0; j < 2; j++)
            #pragma unroll
            for (int r = 0; r < 4; r++) acc2[i][j][r] = 0.f;

    for (int ks = 0; ks < 128; ks += 8) {
        uint32_t af[4][4], bf[2][2];
        #pragma unroll
        for (int mt = 0; mt < 4; mt++) {
            int m = wm * 64 + mt * 16 + g;
            af[mt][0] = tf32u(Wsm[m * 132 + ks + tg]);
            af[mt][1] = tf32u(Wsm[(m + 8) * 132 + ks + tg]);
            af[mt][2] = tf32u(Wsm[m * 132 + ks + tg + 4]);
            af[mt][3] = tf32u(Wsm[(m + 8) * 132 + ks + tg + 4]);
        }
        #pragma unroll
        for (int nt = 0; nt < 2; nt++) {
            int n = wn * 16 + nt * 8 + g;
            bf[nt][0] = FU(Msm[n * 132 + ks + tg]);
            bf[nt][1] = FU(Msm[n * 132 + ks + tg + 4]);
        }
        #pragma unroll
        for (int mt = 0; mt < 4; mt++)
            #pragma unroll
            for (int nt = 0; nt < 2; nt++)
                mma_tf32(acc2[mt][nt], af[mt], bf[nt]);
    }

    #pragma unroll
    for (int mt = 0; mt < 4; mt++) {
        int c2 = wm * 64 + mt * 16 + g;
        #pragma unroll
        for (int nt = 0; nt < 2; nt++) {
            int e = wn * 16 + nt * 8 + tg * 2;
            float* c = acc2[mt][nt];
            *(float2*)(g_M2T + ((size_t)b * C_ + c2) * E_ + blk * 64 + e) =
                make_float2(tf32r(c[0]), tf32r(c[1]));
            *(float2*)(g_M2T + ((size_t)b * C_ + c2 + 8) * E_ + blk * 64 + e) =
                make_float2(tf32r(c[2]), tf32r(c[3]));
        }
    }
}

// ---------------- GEMM3: BM=128, MK layout, STG=3, 2 CTAs/SM -----------------
// out[b][n][c] = DvInv[b][n] * sum_e H[n][e] * M2T[c][e] + bias[c]
#define T3 (128 * 36 * 4)          // 18432
#define DYN3 (3 * 2 * T3)          // 110592

__global__ __launch_bounds__(256, 2) void gemm3_kernel(const float* __restrict__ Hg,
                                                       const float* __restrict__ biasg,
                                                       float* __restrict__ Og) {
    extern __shared__ __align__(16) char ds[];
    __shared__ float scl[128];

    const int tid = threadIdx.x, b = blockIdx.z, blk = blockIdx.x;
    const int lane = tid & 31, wid = tid >> 5;
    const int g = lane >> 2, tg = lane & 3;
    const int wm = wid & 1, wn = wid >> 1;

    const float* Ag = Hg + ((size_t)b * N_ + blk * 128) * E_;
    const float* Bg = g_M2T + (size_t)b * C_ * E_;

    if (tid < 128) scl[tid] = biasg[tid];

    const uint32_t sA = smem_u32(ds), sB = sA + 3 * T3;

    float acc[4][4][4];
    #pragma unroll
    for (int i = 0; i < 4; i++)
        #pragma unroll
        for (int j = 0; j < 4; j++)
            #pragma unroll
            for (int r = 0; r < 4; r++) acc[i][j][r] = 0.f;

    auto issue = [&](int kt) {
        int buf = kt - (kt / 3) * 3;
        #pragma unroll
        for (int i = 0; i < 4; i++) {
            int ch = tid + 256 * i;
            int m = ch >> 3, k4 = (ch & 7) * 4;
            CP16(sA + buf * T3 + (m * 36 + k4) * 4,
                 Ag + (size_t)m * E_ + kt * 32 + k4);
            CP16(sB + buf * T3 + (m * 36 + k4) * 4,
                 Bg + (size_t)m * E_ + kt * 32 + k4);
        }
        CP_COMMIT();
    };

    const int KT = E_ / 32;   // 64
    issue(0); issue(1);

    for (int kt = 0; kt < KT; kt++) {
        if (kt + 2 < KT) issue(kt + 2);
        int rem = KT - 1 - kt;
        if (rem >= 2)      CP_WAIT(2);
        else if (rem == 1) CP_WAIT(1);
        else               CP_WAIT(0);
        __syncthreads();

        int buf = kt - (kt / 3) * 3;
        const float* As = (const float*)(ds + (size_t)buf * T3);
        const float* Bs = (const float*)(ds + (size_t)3 * T3 + (size_t)buf * T3);

        #pragma unroll
        for (int ks = 0; ks < 32; ks += 8) {
            uint32_t af[4][4], bf[4][2];
            #pragma unroll
            for (int mt = 0; mt < 4; mt++) {
                int m = wm * 64 + mt * 16 + g;
                af[mt][0] = tf32u(As[m * 36 + ks + tg]);
                af[mt][1] = tf32u(As[(m + 8) * 36 + ks + tg]);
                af[mt][2] = tf32u(As[m * 36 + ks + tg + 4]);
                af[mt][3] = tf32u(As[(m + 8) * 36 + ks + tg + 4]);
            }
            #pragma unroll
            for (int nt = 0; nt < 4; nt++) {
                int n = wn * 32 + nt * 8 + g;
                bf[nt][0] = FU(Bs[n * 36 + ks + tg]);
                bf[nt][1] = FU(Bs[n * 36 + ks + tg + 4]);
            }
            #pragma unroll
            for (int mt = 0; mt < 4; mt++)
                #pragma unroll
                for (int nt = 0; nt < 4; nt++)
                    mma_tf32(acc[mt][nt], af[mt], bf[nt]);
        }
        __syncthreads();
    }

    #pragma unroll
    for (int mt = 0; mt < 4; mt++) {
        int r = wm * 64 + mt * 16 + g;
        float s0 = g_DvInv[b * N_ + blk * 128 + r];
        float s1 = g_DvInv[b * N_ + blk * 128 + r + 8];
        #pragma unroll
        for (int nt = 0; nt < 4; nt++) {
            int col = wn * 32 + nt * 8 + tg * 2;
            float b0 = scl[col], b1 = scl[col + 1];
            float* c = acc[mt][nt];
            *(float2*)(Og + ((size_t)b * N_ + blk * 128 + r) * C_ + col) =
                make_float2(c[0] * s0 + b0, c[1] * s0 + b1);
            *(float2*)(Og + ((size_t)b * N_ + blk * 128 + r + 8) * C_ + col) =
                make_float2(c[2] * s1 + b0, c[3] * s1 + b1);
        }
    }
}

// ---------------- launch -----------------------------------------------------
extern "C" void kernel_launch(void* const* d_in, const int* in_sizes, int n_in,
                              void* d_out, int out_size) {
    const float *x = nullptr, *H = nullptr, *W = nullptr, *bias = nullptr;
    for (int i = 0; i < n_in; i++) {
        long long s = in_sizes[i];
        if (s == (long long)B_ * N_ * E_)      H = (const float*)d_in[i];
        else if (s == (long long)B_ * N_ * C_) x = (const float*)d_in[i];
        else if (s == (long long)C_ * C_)      W = (const float*)d_in[i];
        else if (s == (long long)C_)           bias = (const float*)d_in[i];
    }
    float* outp = (float*)d_out;

    cudaFuncSetAttribute(gemm1_kernel, cudaFuncAttributeMaxDynamicSharedMemorySize, DYN1);
    cudaFuncSetAttribute(gemm3_kernel, cudaFuncAttributeMaxDynamicSharedMemorySize, DYN3);

    dv_kernel<<<B_ * N_ / 8, dim3(32, 8)>>>(H);
    prep_x<<<(B_ * N_ * C_ / 4) / 256, 256>>>(x);

    // M2T = W (De^-1 H^T (Dv^-1/2 x))^T
    gemm1_kernel<<<dim3(E_ / 64, 1, B_), 256, DYN1>>>(H, W);
    // out = Dv^-1/2 (H M2) + bias
    gemm3_kernel<<<dim3(N_ / 128, 1, B_), 256, DYN3>>>(H, bias, outp);
}